// round 15
// baseline (speedup 1.0000x reference)
#include <cuda_runtime.h>
#include <cstdint>

#define N_IMG 8192

// ---------------- scratch (device globals; no allocations) ----------------
__device__ float    g_Ppart[128 * 1024];     // partial batch sums of x
__device__ float    g_thr[20];               // per-channel BN mean (threshold)
__device__ unsigned g_wp2p[50 * 5 * 8];      // conv2 masks, 8-word padded rows
__device__ unsigned g_wz2[50 * 25];          // conv2 W==0 masks
__device__ int      g_zflag2;                // any zero conv2 weight
__device__ __align__(16) unsigned g_wpl[500 * 40];  // linear sign(W)>0 masks
__device__ unsigned g_wzl[500 * 40];         // linear W==0 masks
__device__ int      g_zflagl;
__device__ float    g_alphal[500];           // linear alpha = mean(|W|, dim=1)
__device__ unsigned g_Bp[N_IMG * 40];        // sign(+1) bit-plane into linear
__device__ unsigned g_Bn[N_IMG * 40];        // sign(-1) bit-plane into linear

// ---------------- K_pre: batch-sum of x per pixel -------------------------
__global__ __launch_bounds__(256) void k_pre(const float* __restrict__ x) {
    int b = blockIdx.x, t = threadIdx.x;
    const float* base = x + (size_t)b * 64 * 1024 + t * 4;
    float4 acc = make_float4(0.f, 0.f, 0.f, 0.f);
    for (int i = 0; i < 64; ++i) {
        float4 v = *(const float4*)(base + (size_t)i * 1024);
        acc.x += v.x; acc.y += v.y; acc.z += v.z; acc.w += v.w;
    }
    *(float4*)(g_Ppart + b * 1024 + t * 4) = acc;
}

// ---------------- K_thr: thresholds (b0) + weight masks (b1-4) + alpha ----
__global__ __launch_bounds__(1024) void k_thr(const float* __restrict__ w1,
                                              const float* __restrict__ w2,
                                              const float* __restrict__ wl) {
    int b = blockIdx.x, t = threadIdx.x;
    if (b == 0) {
        __shared__ double Ps[1024];
        __shared__ double Ts[25];
        double s0 = 0.0, s1 = 0.0;
        for (int i = 0; i < 128; i += 2) {
            s0 += (double)g_Ppart[i * 1024 + t];
            s1 += (double)g_Ppart[(i + 1) * 1024 + t];
        }
        Ps[t] = s0 + s1;
        __syncthreads();
        if (t < 800) {                // 25 taps x 32 lanes, fixed shfl tree
            int g = t >> 5, lane = t & 31;
            int dy = g / 5, dx = g % 5;
            double a = 0.0;
            for (int idx = lane; idx < 784; idx += 32) {
                int i = idx / 28, j = idx % 28;
                a += Ps[(i + dy) * 32 + (j + dx)];
            }
#pragma unroll
            for (int o = 16; o; o >>= 1) a += __shfl_down_sync(0xffffffffu, a, o);
            if (lane == 0) Ts[g] = a;
        }
        __syncthreads();
        if (t < 20) {
            double d = 0.0;
            for (int k = 0; k < 25; ++k) d += (double)w1[t * 25 + k] * Ts[k];
            g_thr[t] = (float)(d / (8192.0 * 28.0 * 28.0));
        }
    } else if (b < 5) {
        int gid = (b - 1) * 1024 + t;            // 0..4095
        if (gid < 1250) {                         // conv2 masks
            int oc = gid / 25, d = gid % 25;
            int dy = d / 5, dx = d % 5;
            unsigned mp = 0, mz = 0;
            for (int c = 0; c < 20; ++c) {
                float w = w2[oc * 500 + c * 25 + d];
                if (w > 0.f) mp |= 1u << c;
                else if (w == 0.f) mz |= 1u << c;
            }
            g_wz2[gid] = mz;
            g_wp2p[(oc * 5 + dy) * 8 + dx] = mp;
            if (dx == 0) {                        // zero the pad words
                g_wp2p[(oc * 5 + dy) * 8 + 5] = 0;
                g_wp2p[(oc * 5 + dy) * 8 + 6] = 0;
                g_wp2p[(oc * 5 + dy) * 8 + 7] = 0;
            }
            if (mz) atomicOr(&g_zflag2, 1);
        }
        for (int e = gid; e < 500 * 40; e += 4096) {  // linear masks
            int j = e / 40, wi = e % 40;
            unsigned mp = 0, mz = 0;
            for (int bit = 0; bit < 32; ++bit) {
                int i = wi * 32 + bit;
                if (i < 1250) {
                    float w = wl[j * 1250 + i];
                    if (w > 0.f) mp |= 1u << bit;
                    else if (w == 0.f) mz |= 1u << bit;
                }
            }
            g_wpl[e] = mp; g_wzl[e] = mz;
            if (mz) atomicOr(&g_zflagl, 1);
        }
    } else {
        int w = (b - 5) * 32 + (t >> 5);         // alpha_l row index, 16 blocks
        int lane = t & 31;
        if (w < 500) {
            double s = 0.0;
            for (int i = lane; i < 1250; i += 32)
                s += fabs((double)wl[w * 1250 + i]);
#pragma unroll
            for (int o = 16; o; o >>= 1) s += __shfl_down_sync(0xffffffffu, s, o);
            if (lane == 0) g_alphal[w] = (float)(s / 1250.0);
        }
    }
}

// ---------------- K_conv: warp-specialized conv1 | conv2 pipeline ---------
// 586 blocks x 7 image-pairs. Warps 0-4 (160 thr): conv1 producer.
// Warps 5-7 (96 thr): conv2 consumer. Double-buffered b1s, 1 syncthreads/iter.
#define ROWW 20                       // padded row width (words)
#define PAIRS_PER_BLK 7
__global__ __launch_bounds__(256, 4) void k_conv(const float* __restrict__ x,
                                                 const float* __restrict__ w1) {
    __shared__ __align__(16) float xs[2][1024];
    __shared__ __align__(16) float ws[20 * 40];   // 8-float padded rows
    __shared__ float thr_s[20];
    __shared__ unsigned b1s[2][2][196];           // [buf][img][pixel]
    __shared__ __align__(16) unsigned BsA[2 * 14 * ROWW];
    __shared__ __align__(16) unsigned BsB[2 * 14 * ROWW];
    __shared__ int PB[2][100];
    __shared__ __align__(16) unsigned Wps[50 * 5 * 8];
    __shared__ __align__(16) unsigned char sPN[2][1280];
    int t = threadIdx.x;
    int pair0 = blockIdx.x * PAIRS_PER_BLK;
    int P = min(PAIRS_PER_BLK, N_IMG / 2 - pair0);

    // --- one-time staging (all threads) ---
    for (int i = t; i < 500; i += 256) {
        int c = i / 25, k = i % 25;
        ws[c * 40 + (k / 5) * 8 + (k % 5)] = w1[i];
    }
    if (t < 20) thr_s[t] = g_thr[t];
    for (int i = t; i < 2000; i += 256) Wps[i] = g_wp2p[i];
    if (t < 60) sPN[t / 30][1250 + (t % 30)] = 0;
    __syncthreads();

    int zf = g_zflag2;
    int isA = t < 160;
    float* xsl = &xs[0][0];

#pragma unroll 1
    for (int it = 0; it <= P; ++it) {
        if (isA) {
            if (it < P) {                               // produce pair `it`
                int n0 = (pair0 + it) * 2;
                const float* xb = x + (size_t)n0 * 1024;
                for (int i = t; i < 2048; i += 160) xsl[i] = xb[i];
                asm volatile("bar.sync 1, 160;" ::: "memory");
                int buf = it & 1;
#pragma unroll 1
                for (int task = t; task < 392; task += 160) {
                    int img = task >= 196;
                    int p = task - img * 196;
                    int py = p / 14, px = p % 14;
                    float xp[6][6];
                    const float* xbp = &xs[img][(py * 2) * 32 + px * 2];
#pragma unroll
                    for (int r = 0; r < 6; ++r) {
#pragma unroll
                        for (int c2 = 0; c2 < 3; ++c2) {
                            float2 v = *(const float2*)(xbp + r * 32 + c2 * 2);
                            xp[r][c2 * 2] = v.x; xp[r][c2 * 2 + 1] = v.y;
                        }
                    }
                    unsigned word = 0;
#pragma unroll 1
                    for (int c = 0; c < 20; ++c) {
                        const float* wc = &ws[c * 40];
                        float a0 = 0.f, a1 = 0.f, a2 = 0.f, a3 = 0.f;
#pragma unroll
                        for (int dy = 0; dy < 5; ++dy) {
                            float4 wq = *(const float4*)(wc + dy * 8);
                            float w4 = wc[dy * 8 + 4];
                            float wv[5] = {wq.x, wq.y, wq.z, wq.w, w4};
#pragma unroll
                            for (int dx = 0; dx < 5; ++dx) {
                                float w = wv[dx];
                                a0 = fmaf(w, xp[dy][dx],         a0);
                                a1 = fmaf(w, xp[dy][dx + 1],     a1);
                                a2 = fmaf(w, xp[dy + 1][dx],     a2);
                                a3 = fmaf(w, xp[dy + 1][dx + 1], a3);
                            }
                        }
                        float m = fmaxf(fmaxf(a0, a1), fmaxf(a2, a3));
                        if (m > thr_s[c]) word |= (1u << c);
                    }
                    b1s[buf][img][p] = word;
                }
            }
        } else {
            if (it > 0) {                               // consume pair `it-1`
                int tB = t - 160;
                int buf = (it - 1) & 1;
                int n0 = (pair0 + it - 1) * 2;
                // expand bits to padded dual-copy layout
                for (int i = tB; i < 392; i += 96) {
                    int img = i / 196, p = i % 196;
                    int y = p / 14, xx = p % 14;
                    unsigned bv = b1s[buf][img][p];
                    BsA[img * 14 * ROWW + y * ROWW + xx] = bv;
                    if (xx >= 2) BsB[img * 14 * ROWW + y * ROWW + xx - 2] = bv;
                }
                asm volatile("bar.sync 2, 96;" ::: "memory");
                // pooled-window popcount sums
                for (int i = tB; i < 200; i += 96) {
                    int img = i / 100, p = i % 100;
                    int y = p / 10, xx = p % 10;
                    const unsigned* B = &BsA[img * 14 * ROWW];
                    int s = 0;
#pragma unroll
                    for (int dy = 0; dy < 5; ++dy)
#pragma unroll
                        for (int dx = 0; dx < 5; ++dx)
                            s += __popc(B[(y + dy) * ROWW + xx + dx]);
                    PB[img][p] = s;
                }
                asm volatile("bar.sync 2, 96;" ::: "memory");
                // main XNOR-conv loop: task = (oc, cx)
#pragma unroll 1
                for (int u = tB; u < 250; u += 96) {
                    int oc = u / 5, cx = u % 5;
                    int odd = cx & 1;
                    const unsigned* P0 = odd ? BsB : BsA;
                    int colbase = odd ? (2 * cx - 2) : (2 * cx);
                    unsigned W[25];
#pragma unroll
                    for (int j = 0; j < 5; ++j) {
                        uint4 wq = *(const uint4*)(&Wps[oc * 40 + j * 8]);
                        W[j * 5] = wq.x; W[j * 5 + 1] = wq.y; W[j * 5 + 2] = wq.z;
                        W[j * 5 + 3] = wq.w; W[j * 5 + 4] = Wps[oc * 40 + j * 8 + 4];
                    }
#pragma unroll 1
                    for (int r = 0; r < 5; ++r) {
#pragma unroll 1
                        for (int img = 0; img < 2; ++img) {
                            const unsigned* bp0 = P0 + img * 14 * ROWW + (2 * r) * ROWW + colbase;
                            int a00 = 0, a01 = 0, a10 = 0, a11 = 0;
#pragma unroll
                            for (int rr = 0; rr < 6; ++rr) {
                                const unsigned* bp = bp0 + rr * ROWW;
                                uint4 q = *(const uint4*)bp;
                                uint2 d2 = *(const uint2*)(bp + 4);
                                unsigned p0 = q.x, p1 = q.y, p2 = q.z,
                                         p3 = q.w, p4 = d2.x, p5 = d2.y;
                                if (rr < 5) {
                                    a00 += __popc(p0 & W[rr * 5]) + __popc(p1 & W[rr * 5 + 1])
                                         + __popc(p2 & W[rr * 5 + 2]) + __popc(p3 & W[rr * 5 + 3])
                                         + __popc(p4 & W[rr * 5 + 4]);
                                    a01 += __popc(p1 & W[rr * 5]) + __popc(p2 & W[rr * 5 + 1])
                                         + __popc(p3 & W[rr * 5 + 2]) + __popc(p4 & W[rr * 5 + 3])
                                         + __popc(p5 & W[rr * 5 + 4]);
                                }
                                if (rr >= 1) {
                                    a10 += __popc(p0 & W[(rr - 1) * 5]) + __popc(p1 & W[(rr - 1) * 5 + 1])
                                         + __popc(p2 & W[(rr - 1) * 5 + 2]) + __popc(p3 & W[(rr - 1) * 5 + 3])
                                         + __popc(p4 & W[(rr - 1) * 5 + 4]);
                                    a11 += __popc(p1 & W[(rr - 1) * 5]) + __popc(p2 & W[(rr - 1) * 5 + 1])
                                         + __popc(p3 & W[(rr - 1) * 5 + 2]) + __popc(p4 & W[(rr - 1) * 5 + 3])
                                         + __popc(p5 & W[(rr - 1) * 5 + 4]);
                                }
                            }
                            int v00 = 2 * a00 - PB[img][(2 * r) * 10 + 2 * cx];
                            int v01 = 2 * a01 - PB[img][(2 * r) * 10 + 2 * cx + 1];
                            int v10 = 2 * a10 - PB[img][(2 * r + 1) * 10 + 2 * cx];
                            int v11 = 2 * a11 - PB[img][(2 * r + 1) * 10 + 2 * cx + 1];
                            if (zf) {  // uniform, never taken with this dataset
                                const unsigned* B = &BsA[img * 14 * ROWW + (2 * r) * ROWW + 2 * cx];
                                int z00 = 0, z01 = 0, z10 = 0, z11 = 0;
                                for (int dy = 0; dy < 5; ++dy)
                                    for (int dx = 0; dx < 5; ++dx) {
                                        unsigned wz = g_wz2[oc * 25 + dy * 5 + dx];
                                        z00 += __popc(B[dy * ROWW + dx] & wz);
                                        z01 += __popc(B[dy * ROWW + dx + 1] & wz);
                                        z10 += __popc(B[(dy + 1) * ROWW + dx] & wz);
                                        z11 += __popc(B[(dy + 1) * ROWW + dx + 1] & wz);
                                    }
                                v00 += z00; v01 += z01; v10 += z10; v11 += z11;
                            }
                            int best = max(max(v00, v01), max(v10, v11));
                            sPN[img][oc * 25 + r * 5 + cx] =
                                (unsigned char)((best > 0 ? 1 : 0) | (best < 0 ? 2 : 0));
                        }
                    }
                }
                asm volatile("bar.sync 2, 96;" ::: "memory");
                // byte planes -> bit planes
                for (int i = tB; i < 80; i += 96) {
                    int img = i / 40, wi = i % 40;
                    const unsigned* src = (const unsigned*)&sPN[img][0] + wi * 8;
                    unsigned Pw = 0, Nw = 0;
#pragma unroll
                    for (int j = 0; j < 8; ++j) {
                        unsigned b = src[j];
                        Pw |= ((((b & 0x01010101u) * 0x00204081u) >> 21) & 0xFu) << (4 * j);
                        Nw |= (((((b >> 1) & 0x01010101u) * 0x00204081u) >> 21) & 0xFu) << (4 * j);
                    }
                    g_Bp[(size_t)(n0 + img) * 40 + wi] = Pw;
                    g_Bn[(size_t)(n0 + img) * 40 + wi] = Nw;
                }
            }
        }
        __syncthreads();              // buffer handoff
    }
}

// ---------------- K4: binary linear + clip + fc — W streamed from gmem ----
#define D_IMGS 16
__global__ __launch_bounds__(512, 2) void k_dense(const float* __restrict__ fcw,
                                                  const float* __restrict__ fcb,
                                                  float* __restrict__ out) {
    __shared__ __align__(16) unsigned Bps[D_IMGS * 40];
    __shared__ __align__(16) unsigned Bns[D_IMGS * 40];
    __shared__ __align__(16) unsigned Us[D_IMGS * 40];
    __shared__ int pcU[D_IMGS];
    __shared__ float hs[D_IMGS * 500];
    int t = threadIdx.x;
    int n0 = blockIdx.x * D_IMGS;
    for (int i = t; i < D_IMGS * 40; i += 512) {
        int img = i / 40, wi = i % 40;
        unsigned bp = g_Bp[(size_t)(n0 + img) * 40 + wi];
        unsigned bn = g_Bn[(size_t)(n0 + img) * 40 + wi];
        Bps[img * 40 + wi] = bp;
        Bns[img * 40 + wi] = bn;
        Us[img * 40 + wi]  = bp | bn;
    }
    __syncthreads();
    if (t < D_IMGS) {
        int s = 0;
        for (int k = 0; k < 40; ++k) s += __popc(Us[t * 40 + k]);
        pcU[t] = s;
    }
    __syncthreads();
    int zf = g_zflagl;
    for (int j = t; j < 500; j += 512) {
        float al = g_alphal[j];
        int m[D_IMGS];
#pragma unroll
        for (int img = 0; img < D_IMGS; ++img) m[img] = 0;
#pragma unroll 1
        for (int half = 0; half < 2; ++half) {
            unsigned wr[20];
#pragma unroll
            for (int k = 0; k < 5; ++k) {
                uint4 q = *(const uint4*)(&g_wpl[j * 40 + half * 20 + k * 4]);
                wr[k * 4] = q.x; wr[k * 4 + 1] = q.y;
                wr[k * 4 + 2] = q.z; wr[k * 4 + 3] = q.w;
            }
#pragma unroll
            for (int img = 0; img < D_IMGS; ++img) {
                const unsigned* Bb = &Bps[img * 40 + half * 20];
                const unsigned* Ub = &Us[img * 40 + half * 20];
                int mm = 0;
#pragma unroll
                for (int k = 0; k < 5; ++k) {
                    uint4 bq = *(const uint4*)(Bb + k * 4);
                    uint4 uq = *(const uint4*)(Ub + k * 4);
                    mm += __popc((~(bq.x ^ wr[k * 4]))     & uq.x);
                    mm += __popc((~(bq.y ^ wr[k * 4 + 1])) & uq.y);
                    mm += __popc((~(bq.z ^ wr[k * 4 + 2])) & uq.z);
                    mm += __popc((~(bq.w ^ wr[k * 4 + 3])) & uq.w);
                }
                m[img] += mm;
            }
        }
#pragma unroll
        for (int img = 0; img < D_IMGS; ++img) {
            int vi = 2 * m[img] - pcU[img];
            if (zf) {  // uniform, never taken with this dataset
                int cp = 0, cn = 0;
                for (int k = 0; k < 40; ++k) {
                    unsigned z = g_wzl[j * 40 + k];
                    cp += __popc(Bps[img * 40 + k] & z);
                    cn += __popc(Bns[img * 40 + k] & z);
                }
                vi += cp - cn;
            }
            float h = fminf(fmaxf((float)vi * al, -1.f), 1.f);
            hs[img * 500 + j] = h;
        }
    }
    __syncthreads();
    int w = t >> 5, lane = t & 31;   // warp w -> image w
    for (int lg = 0; lg < 10; ++lg) {
        float p = 0.f;
        for (int j = lane; j < 500; j += 32)
            p += hs[w * 500 + j] * __ldg(&fcw[lg * 500 + j]);
#pragma unroll
        for (int o = 16; o; o >>= 1) p += __shfl_down_sync(0xffffffffu, p, o);
        if (lane == 0) out[(size_t)(n0 + w) * 10 + lg] = p + fcb[lg];
    }
}

// ---------------- launch ---------------------------------------------------
extern "C" void kernel_launch(void* const* d_in, const int* in_sizes, int n_in,
                              void* d_out, int out_size) {
    const float* x   = (const float*)d_in[0];
    const float* w1  = (const float*)d_in[1];
    const float* w2  = (const float*)d_in[2];
    const float* wl  = (const float*)d_in[3];
    const float* fcw = (const float*)d_in[4];
    const float* fcb = (const float*)d_in[5];
    float* out = (float*)d_out;

    int n_pairs = N_IMG / 2;
    int conv_grid = (n_pairs + PAIRS_PER_BLK - 1) / PAIRS_PER_BLK;   // 586

    k_pre<<<128, 256>>>(x);
    k_thr<<<21, 1024>>>(w1, w2, wl);
    k_conv<<<conv_grid, 256>>>(x, w1);
    k_dense<<<N_IMG / D_IMGS, 512>>>(fcw, fcb, out);
}

// round 16
// speedup vs baseline: 1.1525x; 1.1525x over previous
#include <cuda_runtime.h>
#include <cstdint>

#define N_IMG 8192

// ---------------- scratch (device globals; no allocations) ----------------
__device__ float    g_Ppart[128 * 1024];     // partial batch sums of x
__device__ float    g_thr[20];               // per-channel BN mean (threshold)
__device__ unsigned g_wp2p[50 * 5 * 8];      // conv2 masks, 8-word padded rows
__device__ unsigned g_wz2[50 * 25];          // conv2 W==0 masks
__device__ int      g_zflag2;                // any zero conv2 weight
__device__ __align__(16) unsigned g_wpl[500 * 40];  // linear sign(W)>0 masks
__device__ unsigned g_wzl[500 * 40];         // linear W==0 masks
__device__ int      g_zflagl;
__device__ float    g_alphal[500];           // linear alpha = mean(|W|, dim=1)
__device__ unsigned g_Bp[N_IMG * 40];        // sign(+1) bit-plane into linear
__device__ unsigned g_Bn[N_IMG * 40];        // sign(-1) bit-plane into linear

// ---------------- K_pre: colsum (b<128) + weight masks (b<144) + alpha ----
__global__ __launch_bounds__(256) void k_pre(const float* __restrict__ x,
                                             const float* __restrict__ w2,
                                             const float* __restrict__ wl) {
    int b = blockIdx.x, t = threadIdx.x;
    if (b < 128) {
        const float* base = x + (size_t)b * 64 * 1024 + t * 4;
        float4 acc = make_float4(0.f, 0.f, 0.f, 0.f);
        for (int i = 0; i < 64; ++i) {
            float4 v = *(const float4*)(base + (size_t)i * 1024);
            acc.x += v.x; acc.y += v.y; acc.z += v.z; acc.w += v.w;
        }
        *(float4*)(g_Ppart + b * 1024 + t * 4) = acc;
    } else if (b < 144) {
        int gid = (b - 128) * 256 + t;           // 0..4095
        if (gid < 1250) {                         // conv2 masks (padded rows)
            int oc = gid / 25, d = gid % 25;
            int dy = d / 5, dx = d % 5;
            unsigned mp = 0, mz = 0;
            for (int c = 0; c < 20; ++c) {
                float w = w2[oc * 500 + c * 25 + d];
                if (w > 0.f) mp |= 1u << c;
                else if (w == 0.f) mz |= 1u << c;
            }
            g_wz2[gid] = mz;
            g_wp2p[(oc * 5 + dy) * 8 + dx] = mp;
            if (dx == 0) {                        // zero the pad words
                g_wp2p[(oc * 5 + dy) * 8 + 5] = 0;
                g_wp2p[(oc * 5 + dy) * 8 + 6] = 0;
                g_wp2p[(oc * 5 + dy) * 8 + 7] = 0;
            }
            if (mz) atomicOr(&g_zflag2, 1);
        }
        for (int e = gid; e < 500 * 40; e += 4096) {  // linear masks
            int j = e / 40, wi = e % 40;
            unsigned mp = 0, mz = 0;
            for (int bit = 0; bit < 32; ++bit) {
                int i = wi * 32 + bit;
                if (i < 1250) {
                    float w = wl[j * 1250 + i];
                    if (w > 0.f) mp |= 1u << bit;
                    else if (w == 0.f) mz |= 1u << bit;
                }
            }
            g_wpl[e] = mp; g_wzl[e] = mz;
            if (mz) atomicOr(&g_zflagl, 1);
        }
    } else {
        int w = (b - 144) * 8 + (t >> 5);        // alpha_l row, 63 blocks
        int lane = t & 31;
        if (w < 500) {
            double s = 0.0;
            for (int i = lane; i < 1250; i += 32)
                s += fabs((double)wl[w * 1250 + i]);
#pragma unroll
            for (int o = 16; o; o >>= 1) s += __shfl_down_sync(0xffffffffu, s, o);
            if (lane == 0) g_alphal[w] = (float)(s / 1250.0);
        }
    }
}

// ---------------- K_thr: single block — reduce partials -> thresholds -----
__global__ __launch_bounds__(1024) void k_thr(const float* __restrict__ w1) {
    __shared__ double Ps[1024];
    __shared__ double Ts[25];
    int t = threadIdx.x;
    double s0 = 0.0, s1 = 0.0;
    for (int i = 0; i < 128; i += 2) {
        s0 += (double)g_Ppart[i * 1024 + t];
        s1 += (double)g_Ppart[(i + 1) * 1024 + t];
    }
    Ps[t] = s0 + s1;
    __syncthreads();
    if (t < 800) {                    // 25 taps x 32 lanes, fixed shfl tree
        int g = t >> 5, lane = t & 31;
        int dy = g / 5, dx = g % 5;
        double a = 0.0;
        for (int idx = lane; idx < 784; idx += 32) {
            int i = idx / 28, j = idx % 28;
            a += Ps[(i + dy) * 32 + (j + dx)];
        }
#pragma unroll
        for (int o = 16; o; o >>= 1) a += __shfl_down_sync(0xffffffffu, a, o);
        if (lane == 0) Ts[g] = a;
    }
    __syncthreads();
    if (t < 20) {
        double d = 0.0;
        for (int k = 0; k < 25; ++k) d += (double)w1[t * 25 + k] * Ts[k];
        g_thr[t] = (float)(d / (8192.0 * 28.0 * 28.0));
    }
}

// ---------------- K_conv: fused conv1 + conv2 per 2 images (R14) ----------
#define ROWW 20                       // padded row width (words)
__global__ __launch_bounds__(256) void k_conv(const float* __restrict__ x,
                                              const float* __restrict__ w1) {
    __shared__ __align__(16) float xs[2][1024];
    __shared__ __align__(16) float ws[20 * 40];   // 8-float padded rows
    __shared__ float thr_s[20];
    __shared__ unsigned b1s[2][196];
    __shared__ __align__(16) unsigned BsA[2 * 14 * ROWW];
    __shared__ __align__(16) unsigned BsB[2 * 14 * ROWW];
    __shared__ int PB[2][100];
    __shared__ __align__(16) unsigned Wps[50 * 5 * 8];
    __shared__ __align__(16) unsigned char sPN[2][1280];
    int n0 = blockIdx.x * 2, t = threadIdx.x;

    // --- stage conv1 weights (padded), thresholds, conv2 masks, images ---
    for (int i = t; i < 500; i += 256) {
        int c = i / 25, k = i % 25;
        ws[c * 40 + (k / 5) * 8 + (k % 5)] = w1[i];
    }
    if (t < 20) thr_s[t] = g_thr[t];
    for (int i = t; i < 2000; i += 256) Wps[i] = g_wp2p[i];
    if (t < 60) sPN[t / 30][1250 + (t % 30)] = 0;
    {
        const float* xb = x + (size_t)n0 * 1024;
        for (int i = t; i < 2048; i += 256) xs[0][i] = xb[i];   // [2][1024] linear
    }
    __syncthreads();

    // --- phase 1: conv1 + threshold + pool + bit-pack, flattened tasks ---
#pragma unroll 1
    for (int task = t; task < 392; task += 256) {
        int img = task >= 196;
        int p = task - img * 196;
        int py = p / 14, px = p % 14;
        float xp[6][6];
        const float* xb = &xs[img][(py * 2) * 32 + px * 2];
#pragma unroll
        for (int r = 0; r < 6; ++r) {
#pragma unroll
            for (int c2 = 0; c2 < 3; ++c2) {
                float2 v = *(const float2*)(xb + r * 32 + c2 * 2);
                xp[r][c2 * 2] = v.x; xp[r][c2 * 2 + 1] = v.y;
            }
        }
        unsigned word = 0;
#pragma unroll 1
        for (int c = 0; c < 20; ++c) {
            const float* wc = &ws[c * 40];
            float a0 = 0.f, a1 = 0.f, a2 = 0.f, a3 = 0.f;
#pragma unroll
            for (int dy = 0; dy < 5; ++dy) {
                float4 wq = *(const float4*)(wc + dy * 8);
                float w4 = wc[dy * 8 + 4];
                float wv[5] = {wq.x, wq.y, wq.z, wq.w, w4};
#pragma unroll
                for (int dx = 0; dx < 5; ++dx) {
                    float w = wv[dx];
                    a0 = fmaf(w, xp[dy][dx],         a0);
                    a1 = fmaf(w, xp[dy][dx + 1],     a1);
                    a2 = fmaf(w, xp[dy + 1][dx],     a2);
                    a3 = fmaf(w, xp[dy + 1][dx + 1], a3);
                }
            }
            float m = fmaxf(fmaxf(a0, a1), fmaxf(a2, a3));
            if (m > thr_s[c]) word |= (1u << c);
        }
        b1s[img][p] = word;
    }
    __syncthreads();

    // --- phase 2: XNOR conv2 on smem-resident bits (R8 layout) ---
    for (int i = t; i < 2 * 196; i += 256) {
        int img = i / 196, p = i % 196;
        int y = p / 14, xx = p % 14;
        unsigned bv = b1s[img][p];
        BsA[img * 14 * ROWW + y * ROWW + xx] = bv;
        if (xx >= 2) BsB[img * 14 * ROWW + y * ROWW + xx - 2] = bv;
    }
    __syncthreads();
    for (int i = t; i < 2 * 100; i += 256) {
        int img = i / 100, p = i % 100;
        int y = p / 10, xx = p % 10;
        const unsigned* B = &BsA[img * 14 * ROWW];
        int s = 0;
#pragma unroll
        for (int dy = 0; dy < 5; ++dy)
#pragma unroll
            for (int dx = 0; dx < 5; ++dx)
                s += __popc(B[(y + dy) * ROWW + xx + dx]);
        PB[img][p] = s;
    }
    __syncthreads();
    int zf = g_zflag2;
    if (t < 250) {
        int oc = t / 5, cx = t % 5;
        int odd = cx & 1;
        const unsigned* P0 = odd ? BsB : BsA;
        int colbase = odd ? (2 * cx - 2) : (2 * cx);
        unsigned W[25];
#pragma unroll
        for (int j = 0; j < 5; ++j) {
            uint4 wq = *(const uint4*)(&Wps[oc * 40 + j * 8]);
            W[j * 5] = wq.x; W[j * 5 + 1] = wq.y; W[j * 5 + 2] = wq.z; W[j * 5 + 3] = wq.w;
            W[j * 5 + 4] = Wps[oc * 40 + j * 8 + 4];
        }
#pragma unroll 1
        for (int r = 0; r < 5; ++r) {
#pragma unroll 1
            for (int img = 0; img < 2; ++img) {
                const unsigned* bp0 = P0 + img * 14 * ROWW + (2 * r) * ROWW + colbase;
                int a00 = 0, a01 = 0, a10 = 0, a11 = 0;
#pragma unroll
                for (int rr = 0; rr < 6; ++rr) {
                    const unsigned* bp = bp0 + rr * ROWW;
                    uint4 q = *(const uint4*)bp;
                    uint2 d2 = *(const uint2*)(bp + 4);
                    unsigned p0 = q.x, p1 = q.y, p2 = q.z, p3 = q.w, p4 = d2.x, p5 = d2.y;
                    if (rr < 5) {
                        a00 += __popc(p0 & W[rr * 5]) + __popc(p1 & W[rr * 5 + 1])
                             + __popc(p2 & W[rr * 5 + 2]) + __popc(p3 & W[rr * 5 + 3])
                             + __popc(p4 & W[rr * 5 + 4]);
                        a01 += __popc(p1 & W[rr * 5]) + __popc(p2 & W[rr * 5 + 1])
                             + __popc(p3 & W[rr * 5 + 2]) + __popc(p4 & W[rr * 5 + 3])
                             + __popc(p5 & W[rr * 5 + 4]);
                    }
                    if (rr >= 1) {
                        a10 += __popc(p0 & W[(rr - 1) * 5]) + __popc(p1 & W[(rr - 1) * 5 + 1])
                             + __popc(p2 & W[(rr - 1) * 5 + 2]) + __popc(p3 & W[(rr - 1) * 5 + 3])
                             + __popc(p4 & W[(rr - 1) * 5 + 4]);
                        a11 += __popc(p1 & W[(rr - 1) * 5]) + __popc(p2 & W[(rr - 1) * 5 + 1])
                             + __popc(p3 & W[(rr - 1) * 5 + 2]) + __popc(p4 & W[(rr - 1) * 5 + 3])
                             + __popc(p5 & W[(rr - 1) * 5 + 4]);
                    }
                }
                int v00 = 2 * a00 - PB[img][(2 * r) * 10 + 2 * cx];
                int v01 = 2 * a01 - PB[img][(2 * r) * 10 + 2 * cx + 1];
                int v10 = 2 * a10 - PB[img][(2 * r + 1) * 10 + 2 * cx];
                int v11 = 2 * a11 - PB[img][(2 * r + 1) * 10 + 2 * cx + 1];
                if (zf) {  // uniform, never taken with this dataset
                    const unsigned* B = &BsA[img * 14 * ROWW + (2 * r) * ROWW + 2 * cx];
                    int z00 = 0, z01 = 0, z10 = 0, z11 = 0;
                    for (int dy = 0; dy < 5; ++dy)
                        for (int dx = 0; dx < 5; ++dx) {
                            unsigned wz = g_wz2[oc * 25 + dy * 5 + dx];
                            z00 += __popc(B[dy * ROWW + dx] & wz);
                            z01 += __popc(B[dy * ROWW + dx + 1] & wz);
                            z10 += __popc(B[(dy + 1) * ROWW + dx] & wz);
                            z11 += __popc(B[(dy + 1) * ROWW + dx + 1] & wz);
                        }
                    v00 += z00; v01 += z01; v10 += z10; v11 += z11;
                }
                int best = max(max(v00, v01), max(v10, v11));
                sPN[img][oc * 25 + r * 5 + cx] =
                    (unsigned char)((best > 0 ? 1 : 0) | (best < 0 ? 2 : 0));
            }
        }
    }
    __syncthreads();
    if (t < 2 * 40) {                    // byte planes -> bit planes
        int img = t / 40, wi = t % 40;
        const unsigned* src = (const unsigned*)&sPN[img][0] + wi * 8;
        unsigned P = 0, N = 0;
#pragma unroll
        for (int j = 0; j < 8; ++j) {
            unsigned b = src[j];
            P |= ((((b & 0x01010101u) * 0x00204081u) >> 21) & 0xFu) << (4 * j);
            N |= (((((b >> 1) & 0x01010101u) * 0x00204081u) >> 21) & 0xFu) << (4 * j);
        }
        g_Bp[(size_t)(n0 + img) * 40 + wi] = P;
        g_Bn[(size_t)(n0 + img) * 40 + wi] = N;
    }
}

// ---------------- K4: binary linear + clip + fc — W streamed from gmem ----
#define D_IMGS 16
__global__ __launch_bounds__(512, 2) void k_dense(const float* __restrict__ fcw,
                                                  const float* __restrict__ fcb,
                                                  float* __restrict__ out) {
    __shared__ __align__(16) unsigned Bps[D_IMGS * 40];
    __shared__ __align__(16) unsigned Bns[D_IMGS * 40];
    __shared__ __align__(16) unsigned Us[D_IMGS * 40];
    __shared__ int pcU[D_IMGS];
    __shared__ float hs[D_IMGS * 500];
    int t = threadIdx.x;
    int n0 = blockIdx.x * D_IMGS;
    for (int i = t; i < D_IMGS * 40; i += 512) {
        int img = i / 40, wi = i % 40;
        unsigned bp = g_Bp[(size_t)(n0 + img) * 40 + wi];
        unsigned bn = g_Bn[(size_t)(n0 + img) * 40 + wi];
        Bps[img * 40 + wi] = bp;
        Bns[img * 40 + wi] = bn;
        Us[img * 40 + wi]  = bp | bn;
    }
    __syncthreads();
    if (t < D_IMGS) {
        int s = 0;
        for (int k = 0; k < 40; ++k) s += __popc(Us[t * 40 + k]);
        pcU[t] = s;
    }
    __syncthreads();
    int zf = g_zflagl;
    for (int j = t; j < 500; j += 512) {
        float al = g_alphal[j];
        int m[D_IMGS];
#pragma unroll
        for (int img = 0; img < D_IMGS; ++img) m[img] = 0;
#pragma unroll 1
        for (int half = 0; half < 2; ++half) {
            unsigned wr[20];
#pragma unroll
            for (int k = 0; k < 5; ++k) {
                uint4 q = *(const uint4*)(&g_wpl[j * 40 + half * 20 + k * 4]);
                wr[k * 4] = q.x; wr[k * 4 + 1] = q.y;
                wr[k * 4 + 2] = q.z; wr[k * 4 + 3] = q.w;
            }
#pragma unroll
            for (int img = 0; img < D_IMGS; ++img) {
                const unsigned* Bb = &Bps[img * 40 + half * 20];
                const unsigned* Ub = &Us[img * 40 + half * 20];
                int mm = 0;
#pragma unroll
                for (int k = 0; k < 5; ++k) {
                    uint4 bq = *(const uint4*)(Bb + k * 4);
                    uint4 uq = *(const uint4*)(Ub + k * 4);
                    mm += __popc((~(bq.x ^ wr[k * 4]))     & uq.x);
                    mm += __popc((~(bq.y ^ wr[k * 4 + 1])) & uq.y);
                    mm += __popc((~(bq.z ^ wr[k * 4 + 2])) & uq.z);
                    mm += __popc((~(bq.w ^ wr[k * 4 + 3])) & uq.w);
                }
                m[img] += mm;
            }
        }
#pragma unroll
        for (int img = 0; img < D_IMGS; ++img) {
            int vi = 2 * m[img] - pcU[img];
            if (zf) {  // uniform, never taken with this dataset
                int cp = 0, cn = 0;
                for (int k = 0; k < 40; ++k) {
                    unsigned z = g_wzl[j * 40 + k];
                    cp += __popc(Bps[img * 40 + k] & z);
                    cn += __popc(Bns[img * 40 + k] & z);
                }
                vi += cp - cn;
            }
            float h = fminf(fmaxf((float)vi * al, -1.f), 1.f);
            hs[img * 500 + j] = h;
        }
    }
    __syncthreads();
    int w = t >> 5, lane = t & 31;   // warp w -> image w
    for (int lg = 0; lg < 10; ++lg) {
        float p = 0.f;
        for (int j = lane; j < 500; j += 32)
            p += hs[w * 500 + j] * __ldg(&fcw[lg * 500 + j]);
#pragma unroll
        for (int o = 16; o; o >>= 1) p += __shfl_down_sync(0xffffffffu, p, o);
        if (lane == 0) out[(size_t)(n0 + w) * 10 + lg] = p + fcb[lg];
    }
}

// ---------------- launch ---------------------------------------------------
extern "C" void kernel_launch(void* const* d_in, const int* in_sizes, int n_in,
                              void* d_out, int out_size) {
    const float* x   = (const float*)d_in[0];
    const float* w1  = (const float*)d_in[1];
    const float* w2  = (const float*)d_in[2];
    const float* wl  = (const float*)d_in[3];
    const float* fcw = (const float*)d_in[4];
    const float* fcb = (const float*)d_in[5];
    float* out = (float*)d_out;

    k_pre<<<207, 256>>>(x, w2, wl);
    k_thr<<<1, 1024>>>(w1);
    k_conv<<<N_IMG / 2, 256>>>(x, w1);
    k_dense<<<N_IMG / D_IMGS, 512>>>(fcw, fcb, out);
}

// round 17
// speedup vs baseline: 1.1626x; 1.0088x over previous
#include <cuda_runtime.h>
#include <cstdint>

#define N_IMG 8192

// ---------------- scratch (device globals; no allocations) ----------------
__device__ float    g_Ppart[128 * 1024];     // partial batch sums of x
__device__ float    g_thr[20];               // per-channel BN mean (threshold)
__device__ unsigned g_wp2p[50 * 5 * 8];      // conv2 masks, 8-word padded rows
__device__ unsigned g_wz2[50 * 25];          // conv2 W==0 masks
__device__ int      g_zflag2;                // any zero conv2 weight
__device__ __align__(16) unsigned g_wpl[500 * 40];  // linear sign(W)>0 masks
__device__ unsigned g_wzl[500 * 40];         // linear W==0 masks
__device__ int      g_zflagl;
__device__ float    g_alphal[500];           // linear alpha = mean(|W|, dim=1)
__device__ unsigned g_Bp[N_IMG * 40];        // sign(+1) bit-plane into linear
__device__ unsigned g_Bn[N_IMG * 40];        // sign(-1) bit-plane into linear

// ---------------- K_pre: batch-sum of x per pixel -------------------------
__global__ __launch_bounds__(256) void k_pre(const float* __restrict__ x) {
    int b = blockIdx.x, t = threadIdx.x;
    const float* base = x + (size_t)b * 64 * 1024 + t * 4;
    float4 acc = make_float4(0.f, 0.f, 0.f, 0.f);
    for (int i = 0; i < 64; ++i) {
        float4 v = *(const float4*)(base + (size_t)i * 1024);
        acc.x += v.x; acc.y += v.y; acc.z += v.z; acc.w += v.w;
    }
    *(float4*)(g_Ppart + b * 1024 + t * 4) = acc;
}

// ---------------- K_thr: thresholds (b0) + weight masks (b1-4) + alpha ----
__global__ __launch_bounds__(1024) void k_thr(const float* __restrict__ w1,
                                              const float* __restrict__ w2,
                                              const float* __restrict__ wl) {
    int b = blockIdx.x, t = threadIdx.x;
    if (b == 0) {
        __shared__ double Ps[1024];
        __shared__ double Ts[25];
        double s0 = 0.0, s1 = 0.0;
        for (int i = 0; i < 128; i += 2) {
            s0 += (double)g_Ppart[i * 1024 + t];
            s1 += (double)g_Ppart[(i + 1) * 1024 + t];
        }
        Ps[t] = s0 + s1;
        __syncthreads();
        if (t < 800) {                // 25 taps x 32 lanes, fixed shfl tree
            int g = t >> 5, lane = t & 31;
            int dy = g / 5, dx = g % 5;
            double a = 0.0;
            for (int idx = lane; idx < 784; idx += 32) {
                int i = idx / 28, j = idx % 28;
                a += Ps[(i + dy) * 32 + (j + dx)];
            }
#pragma unroll
            for (int o = 16; o; o >>= 1) a += __shfl_down_sync(0xffffffffu, a, o);
            if (lane == 0) Ts[g] = a;
        }
        __syncthreads();
        if (t < 20) {
            double d = 0.0;
            for (int k = 0; k < 25; ++k) d += (double)w1[t * 25 + k] * Ts[k];
            g_thr[t] = (float)(d / (8192.0 * 28.0 * 28.0));
        }
    } else if (b < 5) {
        int gid = (b - 1) * 1024 + t;            // 0..4095
        if (gid < 1250) {                         // conv2 masks
            int oc = gid / 25, d = gid % 25;
            int dy = d / 5, dx = d % 5;
            unsigned mp = 0, mz = 0;
            for (int c = 0; c < 20; ++c) {
                float w = w2[oc * 500 + c * 25 + d];
                if (w > 0.f) mp |= 1u << c;
                else if (w == 0.f) mz |= 1u << c;
            }
            g_wz2[gid] = mz;
            g_wp2p[(oc * 5 + dy) * 8 + dx] = mp;
            if (dx == 0) {                        // zero the pad words
                g_wp2p[(oc * 5 + dy) * 8 + 5] = 0;
                g_wp2p[(oc * 5 + dy) * 8 + 6] = 0;
                g_wp2p[(oc * 5 + dy) * 8 + 7] = 0;
            }
            if (mz) atomicOr(&g_zflag2, 1);
        }
        for (int e = gid; e < 500 * 40; e += 4096) {  // linear masks
            int j = e / 40, wi = e % 40;
            unsigned mp = 0, mz = 0;
            for (int bit = 0; bit < 32; ++bit) {
                int i = wi * 32 + bit;
                if (i < 1250) {
                    float w = wl[j * 1250 + i];
                    if (w > 0.f) mp |= 1u << bit;
                    else if (w == 0.f) mz |= 1u << bit;
                }
            }
            g_wpl[e] = mp; g_wzl[e] = mz;
            if (mz) atomicOr(&g_zflagl, 1);
        }
    } else {
        int w = (b - 5) * 32 + (t >> 5);         // alpha_l row index, 16 blocks
        int lane = t & 31;
        if (w < 500) {
            double s = 0.0;
            for (int i = lane; i < 1250; i += 32)
                s += fabs((double)wl[w * 1250 + i]);
#pragma unroll
            for (int o = 16; o; o >>= 1) s += __shfl_down_sync(0xffffffffu, s, o);
            if (lane == 0) g_alphal[w] = (float)(s / 1250.0);
        }
    }
}

// ---------------- K_conv: fused conv1 + conv2 per 4 images ----------------
#define ROWW 20                       // padded row width (words)
#define CI 4                          // images per block
__global__ __launch_bounds__(256) void k_conv(const float* __restrict__ x,
                                              const float* __restrict__ w1) {
    __shared__ __align__(16) float xs[CI][1024];
    __shared__ __align__(16) float ws[20 * 40];   // 8-float padded rows
    __shared__ float thr_s[20];
    __shared__ unsigned b1s[CI][196];
    __shared__ __align__(16) unsigned BsA[CI * 14 * ROWW];
    __shared__ __align__(16) unsigned BsB[CI * 14 * ROWW];
    __shared__ int PB[CI][100];
    __shared__ __align__(16) unsigned Wps[50 * 5 * 8];
    __shared__ __align__(16) unsigned char sPN[CI][1280];
    int n0 = blockIdx.x * CI, t = threadIdx.x;

    // --- stage conv1 weights (padded), thresholds, conv2 masks, images ---
    for (int i = t; i < 500; i += 256) {
        int c = i / 25, k = i % 25;
        ws[c * 40 + (k / 5) * 8 + (k % 5)] = w1[i];
    }
    if (t < 20) thr_s[t] = g_thr[t];
    for (int i = t; i < 2000; i += 256) Wps[i] = g_wp2p[i];
    for (int i = t; i < CI * 30; i += 256) sPN[i / 30][1250 + (i % 30)] = 0;
    {
        const float* xb = x + (size_t)n0 * 1024;
        for (int i = t; i < CI * 1024; i += 256) xs[0][i] = xb[i];  // linear
    }
    __syncthreads();

    // --- phase 1: conv1 + threshold + pool + bit-pack, flattened tasks ---
#pragma unroll 1
    for (int task = t; task < CI * 196; task += 256) {
        int img = task / 196;
        int p = task - img * 196;
        int py = p / 14, px = p % 14;
        float xp[6][6];
        const float* xb = &xs[img][(py * 2) * 32 + px * 2];
#pragma unroll
        for (int r = 0; r < 6; ++r) {
#pragma unroll
            for (int c2 = 0; c2 < 3; ++c2) {
                float2 v = *(const float2*)(xb + r * 32 + c2 * 2);
                xp[r][c2 * 2] = v.x; xp[r][c2 * 2 + 1] = v.y;
            }
        }
        unsigned word = 0;
#pragma unroll 1
        for (int c = 0; c < 20; ++c) {
            const float* wc = &ws[c * 40];
            float a0 = 0.f, a1 = 0.f, a2 = 0.f, a3 = 0.f;
#pragma unroll
            for (int dy = 0; dy < 5; ++dy) {
                float4 wq = *(const float4*)(wc + dy * 8);
                float w4 = wc[dy * 8 + 4];
                float wv[5] = {wq.x, wq.y, wq.z, wq.w, w4};
#pragma unroll
                for (int dx = 0; dx < 5; ++dx) {
                    float w = wv[dx];
                    a0 = fmaf(w, xp[dy][dx],         a0);
                    a1 = fmaf(w, xp[dy][dx + 1],     a1);
                    a2 = fmaf(w, xp[dy + 1][dx],     a2);
                    a3 = fmaf(w, xp[dy + 1][dx + 1], a3);
                }
            }
            float m = fmaxf(fmaxf(a0, a1), fmaxf(a2, a3));
            if (m > thr_s[c]) word |= (1u << c);
        }
        b1s[img][p] = word;
    }
    __syncthreads();

    // --- phase 2: XNOR conv2 on smem-resident bits ---
    for (int i = t; i < CI * 196; i += 256) {
        int img = i / 196, p = i % 196;
        int y = p / 14, xx = p % 14;
        unsigned bv = b1s[img][p];
        BsA[img * 14 * ROWW + y * ROWW + xx] = bv;
        if (xx >= 2) BsB[img * 14 * ROWW + y * ROWW + xx - 2] = bv;
    }
    __syncthreads();
    for (int i = t; i < CI * 100; i += 256) {
        int img = i / 100, p = i % 100;
        int y = p / 10, xx = p % 10;
        const unsigned* B = &BsA[img * 14 * ROWW];
        int s = 0;
#pragma unroll
        for (int dy = 0; dy < 5; ++dy)
#pragma unroll
            for (int dx = 0; dx < 5; ++dx)
                s += __popc(B[(y + dy) * ROWW + xx + dx]);
        PB[img][p] = s;
    }
    __syncthreads();
    int zf = g_zflag2;
    if (t < 250) {
        int oc = t / 5, cx = t % 5;
        int odd = cx & 1;
        const unsigned* P0 = odd ? BsB : BsA;
        int colbase = odd ? (2 * cx - 2) : (2 * cx);
        unsigned W[25];
#pragma unroll
        for (int j = 0; j < 5; ++j) {
            uint4 wq = *(const uint4*)(&Wps[oc * 40 + j * 8]);
            W[j * 5] = wq.x; W[j * 5 + 1] = wq.y; W[j * 5 + 2] = wq.z; W[j * 5 + 3] = wq.w;
            W[j * 5 + 4] = Wps[oc * 40 + j * 8 + 4];
        }
#pragma unroll 1
        for (int r = 0; r < 5; ++r) {
#pragma unroll 1
            for (int img = 0; img < CI; ++img) {
                const unsigned* bp0 = P0 + img * 14 * ROWW + (2 * r) * ROWW + colbase;
                int a00 = 0, a01 = 0, a10 = 0, a11 = 0;
#pragma unroll
                for (int rr = 0; rr < 6; ++rr) {
                    const unsigned* bp = bp0 + rr * ROWW;
                    uint4 q = *(const uint4*)bp;
                    uint2 d2 = *(const uint2*)(bp + 4);
                    unsigned p0 = q.x, p1 = q.y, p2 = q.z, p3 = q.w, p4 = d2.x, p5 = d2.y;
                    if (rr < 5) {
                        a00 += __popc(p0 & W[rr * 5]) + __popc(p1 & W[rr * 5 + 1])
                             + __popc(p2 & W[rr * 5 + 2]) + __popc(p3 & W[rr * 5 + 3])
                             + __popc(p4 & W[rr * 5 + 4]);
                        a01 += __popc(p1 & W[rr * 5]) + __popc(p2 & W[rr * 5 + 1])
                             + __popc(p3 & W[rr * 5 + 2]) + __popc(p4 & W[rr * 5 + 3])
                             + __popc(p5 & W[rr * 5 + 4]);
                    }
                    if (rr >= 1) {
                        a10 += __popc(p0 & W[(rr - 1) * 5]) + __popc(p1 & W[(rr - 1) * 5 + 1])
                             + __popc(p2 & W[(rr - 1) * 5 + 2]) + __popc(p3 & W[(rr - 1) * 5 + 3])
                             + __popc(p4 & W[(rr - 1) * 5 + 4]);
                        a11 += __popc(p1 & W[(rr - 1) * 5]) + __popc(p2 & W[(rr - 1) * 5 + 1])
                             + __popc(p3 & W[(rr - 1) * 5 + 2]) + __popc(p4 & W[(rr - 1) * 5 + 3])
                             + __popc(p5 & W[(rr - 1) * 5 + 4]);
                    }
                }
                int v00 = 2 * a00 - PB[img][(2 * r) * 10 + 2 * cx];
                int v01 = 2 * a01 - PB[img][(2 * r) * 10 + 2 * cx + 1];
                int v10 = 2 * a10 - PB[img][(2 * r + 1) * 10 + 2 * cx];
                int v11 = 2 * a11 - PB[img][(2 * r + 1) * 10 + 2 * cx + 1];
                if (zf) {  // uniform, never taken with this dataset
                    const unsigned* B = &BsA[img * 14 * ROWW + (2 * r) * ROWW + 2 * cx];
                    int z00 = 0, z01 = 0, z10 = 0, z11 = 0;
                    for (int dy = 0; dy < 5; ++dy)
                        for (int dx = 0; dx < 5; ++dx) {
                            unsigned wz = g_wz2[oc * 25 + dy * 5 + dx];
                            z00 += __popc(B[dy * ROWW + dx] & wz);
                            z01 += __popc(B[dy * ROWW + dx + 1] & wz);
                            z10 += __popc(B[(dy + 1) * ROWW + dx] & wz);
                            z11 += __popc(B[(dy + 1) * ROWW + dx + 1] & wz);
                        }
                    v00 += z00; v01 += z01; v10 += z10; v11 += z11;
                }
                int best = max(max(v00, v01), max(v10, v11));
                sPN[img][oc * 25 + r * 5 + cx] =
                    (unsigned char)((best > 0 ? 1 : 0) | (best < 0 ? 2 : 0));
            }
        }
    }
    __syncthreads();
    for (int i = t; i < CI * 40; i += 256) {     // byte planes -> bit planes
        int img = i / 40, wi = i % 40;
        const unsigned* src = (const unsigned*)&sPN[img][0] + wi * 8;
        unsigned P = 0, N = 0;
#pragma unroll
        for (int j = 0; j < 8; ++j) {
            unsigned b = src[j];
            P |= ((((b & 0x01010101u) * 0x00204081u) >> 21) & 0xFu) << (4 * j);
            N |= (((((b >> 1) & 0x01010101u) * 0x00204081u) >> 21) & 0xFu) << (4 * j);
        }
        g_Bp[(size_t)(n0 + img) * 40 + wi] = P;
        g_Bn[(size_t)(n0 + img) * 40 + wi] = N;
    }
}

// ---------------- K4: binary linear + clip + fc — W streamed from gmem ----
#define D_IMGS 16
__global__ __launch_bounds__(512, 2) void k_dense(const float* __restrict__ fcw,
                                                  const float* __restrict__ fcb,
                                                  float* __restrict__ out) {
    __shared__ __align__(16) unsigned Bps[D_IMGS * 40];
    __shared__ __align__(16) unsigned Bns[D_IMGS * 40];
    __shared__ __align__(16) unsigned Us[D_IMGS * 40];
    __shared__ int pcU[D_IMGS];
    __shared__ float hs[D_IMGS * 500];
    int t = threadIdx.x;
    int n0 = blockIdx.x * D_IMGS;
    for (int i = t; i < D_IMGS * 40; i += 512) {
        int img = i / 40, wi = i % 40;
        unsigned bp = g_Bp[(size_t)(n0 + img) * 40 + wi];
        unsigned bn = g_Bn[(size_t)(n0 + img) * 40 + wi];
        Bps[img * 40 + wi] = bp;
        Bns[img * 40 + wi] = bn;
        Us[img * 40 + wi]  = bp | bn;
    }
    __syncthreads();
    if (t < D_IMGS) {
        int s = 0;
        for (int k = 0; k < 40; ++k) s += __popc(Us[t * 40 + k]);
        pcU[t] = s;
    }
    __syncthreads();
    int zf = g_zflagl;
    for (int j = t; j < 500; j += 512) {
        float al = g_alphal[j];
        int m[D_IMGS];
#pragma unroll
        for (int img = 0; img < D_IMGS; ++img) m[img] = 0;
#pragma unroll 1
        for (int half = 0; half < 2; ++half) {
            unsigned wr[20];
#pragma unroll
            for (int k = 0; k < 5; ++k) {
                uint4 q = *(const uint4*)(&g_wpl[j * 40 + half * 20 + k * 4]);
                wr[k * 4] = q.x; wr[k * 4 + 1] = q.y;
                wr[k * 4 + 2] = q.z; wr[k * 4 + 3] = q.w;
            }
#pragma unroll
            for (int img = 0; img < D_IMGS; ++img) {
                const unsigned* Bb = &Bps[img * 40 + half * 20];
                const unsigned* Ub = &Us[img * 40 + half * 20];
                int mm = 0;
#pragma unroll
                for (int k = 0; k < 5; ++k) {
                    uint4 bq = *(const uint4*)(Bb + k * 4);
                    uint4 uq = *(const uint4*)(Ub + k * 4);
                    mm += __popc((~(bq.x ^ wr[k * 4]))     & uq.x);
                    mm += __popc((~(bq.y ^ wr[k * 4 + 1])) & uq.y);
                    mm += __popc((~(bq.z ^ wr[k * 4 + 2])) & uq.z);
                    mm += __popc((~(bq.w ^ wr[k * 4 + 3])) & uq.w);
                }
                m[img] += mm;
            }
        }
#pragma unroll
        for (int img = 0; img < D_IMGS; ++img) {
            int vi = 2 * m[img] - pcU[img];
            if (zf) {  // uniform, never taken with this dataset
                int cp = 0, cn = 0;
                for (int k = 0; k < 40; ++k) {
                    unsigned z = g_wzl[j * 40 + k];
                    cp += __popc(Bps[img * 40 + k] & z);
                    cn += __popc(Bns[img * 40 + k] & z);
                }
                vi += cp - cn;
            }
            float h = fminf(fmaxf((float)vi * al, -1.f), 1.f);
            hs[img * 500 + j] = h;
        }
    }
    __syncthreads();
    int w = t >> 5, lane = t & 31;   // warp w -> image w
    for (int lg = 0; lg < 10; ++lg) {
        float p = 0.f;
        for (int j = lane; j < 500; j += 32)
            p += hs[w * 500 + j] * __ldg(&fcw[lg * 500 + j]);
#pragma unroll
        for (int o = 16; o; o >>= 1) p += __shfl_down_sync(0xffffffffu, p, o);
        if (lane == 0) out[(size_t)(n0 + w) * 10 + lg] = p + fcb[lg];
    }
}

// ---------------- launch ---------------------------------------------------
extern "C" void kernel_launch(void* const* d_in, const int* in_sizes, int n_in,
                              void* d_out, int out_size) {
    const float* x   = (const float*)d_in[0];
    const float* w1  = (const float*)d_in[1];
    const float* w2  = (const float*)d_in[2];
    const float* wl  = (const float*)d_in[3];
    const float* fcw = (const float*)d_in[4];
    const float* fcb = (const float*)d_in[5];
    float* out = (float*)d_out;

    k_pre<<<128, 256>>>(x);
    k_thr<<<21, 1024>>>(w1, w2, wl);
    k_conv<<<N_IMG / CI, 256>>>(x, w1);
    k_dense<<<N_IMG / D_IMGS, 512>>>(fcw, fcb, out);
}